// round 5
// baseline (speedup 1.0000x reference)
#include <cuda_runtime.h>
#include <cuda_fp16.h>

#define MAXN 100000
#define MAXE 1600000
#define NROWS 128

typedef unsigned long long u64;

// Packed fp32x2 helpers (sm_100+ FFMA2 path — only reachable via PTX)
__device__ __forceinline__ u64 pk2(float lo, float hi) {
  u64 r;
  asm("mov.b64 %0, {%1, %2};" : "=l"(r) : "f"(lo), "f"(hi));
  return r;
}
__device__ __forceinline__ void fma2(u64& d, u64 a, u64 b) {
  asm("fma.rn.f32x2 %0, %1, %2, %0;" : "+l"(d) : "l"(a), "l"(b));
}
__device__ __forceinline__ float2 upk2(u64 v) {
  float2 f;
  asm("mov.b64 {%0, %1}, %2;" : "=f"(f.x), "=f"(f.y) : "l"(v));
  return f;
}

// Persistent scratch (no allocations allowed).
__device__ float4 g_h4[MAXN * 16];    // h:   N x 64 (fp32)
__device__ float4 g_Mh4[MAXN * 8];    // M:   N x 64 (fp16, packed)
__device__ float4 g_agg4[MAXN * 16];  // agg: N x 64 (fp32)
// CSR (built once per launch from edge_index)
__device__ int g_counts[MAXN];
__device__ int g_rowstart[MAXN];
__device__ int g_rowend[MAXN];
__device__ int g_csrsrc[MAXE];
__device__ int g_blocksum[128];

// ---------------------------------------------------------------------------
// h = relu(x @ w_in + b_in)
// ---------------------------------------------------------------------------
__global__ void __launch_bounds__(256) input_kernel(
    const float* __restrict__ x, const float* __restrict__ w_in,
    const float* __restrict__ b_in, int N) {
  int i = blockIdx.x * blockDim.x + threadIdx.x;
  if (i >= N * 64) return;
  int node = i >> 6, c = i & 63;
  float acc = __ldg(b_in + c);
  acc = fmaf(__ldg(x + node * 3 + 0), __ldg(w_in + c), acc);
  acc = fmaf(__ldg(x + node * 3 + 1), __ldg(w_in + 64 + c), acc);
  acc = fmaf(__ldg(x + node * 3 + 2), __ldg(w_in + 128 + c), acc);
  ((float*)g_h4)[i] = fmaxf(acc, 0.f);
}

// ---------------------------------------------------------------------------
// CSR build
// ---------------------------------------------------------------------------
__global__ void __launch_bounds__(256) zero_counts_kernel(int N) {
  int i = blockIdx.x * blockDim.x + threadIdx.x;
  if (i < N) g_counts[i] = 0;
}

__global__ void __launch_bounds__(256) hist_kernel(const int* __restrict__ ei,
                                                   int E) {
  int e = blockIdx.x * blockDim.x + threadIdx.x;
  if (e < E) atomicAdd(&g_counts[__ldg(ei + E + e)], 1);
}

__global__ void __launch_bounds__(1024) scan1_kernel(int N) {
  __shared__ int sh[1024];
  int t = threadIdx.x;
  int idx = blockIdx.x * 1024 + t;
  int v = (idx < N) ? g_counts[idx] : 0;
  sh[t] = v;
  __syncthreads();
#pragma unroll
  for (int off = 1; off < 1024; off <<= 1) {
    int x = (t >= off) ? sh[t - off] : 0;
    __syncthreads();
    sh[t] += x;
    __syncthreads();
  }
  if (idx < N) g_rowstart[idx] = sh[t] - v;
  if (t == 1023) g_blocksum[blockIdx.x] = sh[1023];
}

__global__ void scan2_kernel(int nb) {
  if (threadIdx.x == 0 && blockIdx.x == 0) {
    int acc = 0;
    for (int i = 0; i < nb; i++) {
      int tmp = g_blocksum[i];
      g_blocksum[i] = acc;
      acc += tmp;
    }
  }
}

__global__ void __launch_bounds__(256) scan3_kernel(int N) {
  int i = blockIdx.x * blockDim.x + threadIdx.x;
  if (i < N) {
    int v = g_rowstart[i] + g_blocksum[i >> 10];
    g_rowstart[i] = v;
    g_rowend[i] = v;
  }
}

__global__ void __launch_bounds__(256) fill_kernel(const int* __restrict__ ei,
                                                   int E) {
  int e = blockIdx.x * blockDim.x + threadIdx.x;
  if (e < E) {
    int d = __ldg(ei + E + e);
    int pos = atomicAdd(&g_rowend[d], 1);
    g_csrsrc[pos] = __ldg(ei + e);
  }
}

// ---------------------------------------------------------------------------
// agg[i] = sum_{e: dst(e)=i} M[src(e)]   (warp per node, conflict-free)
// ---------------------------------------------------------------------------
__global__ void __launch_bounds__(256) gather_kernel(int N) {
  int w = (blockIdx.x * blockDim.x + threadIdx.x) >> 5;
  int lane = threadIdx.x & 31;
  if (w >= N) return;
  int s = __ldg(&g_rowstart[w]);
  int e = __ldg(&g_rowend[w]);
  const __half2* M = (const __half2*)g_Mh4;
  float2 a0 = make_float2(0.f, 0.f), a1 = make_float2(0.f, 0.f);
  int j = s;
  for (; j + 2 <= e; j += 2) {
    int s0 = __ldg(&g_csrsrc[j]);
    int s1 = __ldg(&g_csrsrc[j + 1]);
    float2 v0 = __half22float2(__ldg(&M[(size_t)s0 * 32 + lane]));
    float2 v1 = __half22float2(__ldg(&M[(size_t)s1 * 32 + lane]));
    a0.x += v0.x; a0.y += v0.y;
    a1.x += v1.x; a1.y += v1.y;
  }
  if (j < e) {
    int s0 = __ldg(&g_csrsrc[j]);
    float2 v0 = __half22float2(__ldg(&M[(size_t)s0 * 32 + lane]));
    a0.x += v0.x; a0.y += v0.y;
  }
  ((float2*)g_agg4)[(size_t)w * 32 + lane] =
      make_float2(a0.x + a1.x, a0.y + a1.y);
}

// Packed GEMM micro-step: rows packed in pairs (free from float4 loads),
// 8 B splats, 32 FFMA2.
#define GEMM_STEP(ASRC, BSRC)                                              \
  {                                                                        \
    const float4* ap = (const float4*)(ASRC);                              \
    float4 a0 = ap[0], a1 = ap[1];                                         \
    const float4* bp = (const float4*)(BSRC);                              \
    float4 b0 = bp[0], b1 = bp[1];                                         \
    u64 apk[4] = {pk2(a0.x, a0.y), pk2(a0.z, a0.w), pk2(a1.x, a1.y),       \
                  pk2(a1.z, a1.w)};                                        \
    float bvv[8] = {b0.x, b0.y, b0.z, b0.w, b1.x, b1.y, b1.z, b1.w};       \
    _Pragma("unroll") for (int cc = 0; cc < 8; cc++) {                     \
      u64 bs = pk2(bvv[cc], bvv[cc]);                                      \
      _Pragma("unroll") for (int rp = 0; rp < 4; rp++)                     \
          fma2(accp[rp][cc], apk[rp], bs);                                 \
    }                                                                      \
  }

// ---------------------------------------------------------------------------
// msg: M = relu(h @ W1 + b1) @ W2 + b2  (fp32, packed FFMA2, fp16 output)
// Block: 128 threads (16x8), tile 128 rows x 64 cols, 8x8 per thread.
// ---------------------------------------------------------------------------
__global__ void __launch_bounds__(128) msg_kernel(
    const float* __restrict__ W1, const float* __restrict__ B1,
    const float* __restrict__ W2, const float* __restrict__ B2, int N) {
  extern __shared__ float sm[];
  float* as  = sm;              // 64 * 128 (A transposed, reused for t)
  float* w1s = sm + 64 * 128;   // 64 * 64
  float* w2s = w1s + 64 * 64;   // 64 * 64

  const float* hin = (const float*)g_h4;
  int tid = threadIdx.x;
  int rb = blockIdx.x * NROWS;

#pragma unroll
  for (int i = tid; i < 1024; i += 128) {
    ((float4*)w1s)[i] = __ldg((const float4*)W1 + i);
    ((float4*)w2s)[i] = __ldg((const float4*)W2 + i);
  }
  {
    int r = tid, grow = rb + r;
    if (grow < N) {
      const float4* src = (const float4*)(hin + (size_t)grow * 64);
#pragma unroll
      for (int kq = 0; kq < 16; kq++) {
        float4 v = src[kq];
        as[(kq * 4 + 0) * 128 + r] = v.x;
        as[(kq * 4 + 1) * 128 + r] = v.y;
        as[(kq * 4 + 2) * 128 + r] = v.z;
        as[(kq * 4 + 3) * 128 + r] = v.w;
      }
    } else {
#pragma unroll
      for (int k = 0; k < 64; k++) as[k * 128 + r] = 0.f;
    }
  }
  __syncthreads();

  int ty = tid >> 3, tx = tid & 7;
  int r0 = ty * 8, c0 = tx * 8;

  u64 accp[4][8];
#pragma unroll
  for (int rp = 0; rp < 4; rp++)
#pragma unroll
    for (int cc = 0; cc < 8; cc++) accp[rp][cc] = 0ull;

#pragma unroll 4
  for (int k = 0; k < 64; k++)
    GEMM_STEP(as + k * 128 + r0, w1s + k * 64 + c0);

  __syncthreads();  // stage-1 reads done; overwrite `as` with t (transposed)
#pragma unroll
  for (int cc = 0; cc < 8; cc++) {
    float b = __ldg(B1 + c0 + cc);
#pragma unroll
    for (int rp = 0; rp < 4; rp++) {
      float2 v = upk2(accp[rp][cc]);
      as[(c0 + cc) * 128 + (r0 + 2 * rp)] = fmaxf(v.x + b, 0.f);
      as[(c0 + cc) * 128 + (r0 + 2 * rp + 1)] = fmaxf(v.y + b, 0.f);
    }
  }
  __syncthreads();

#pragma unroll
  for (int rp = 0; rp < 4; rp++)
#pragma unroll
    for (int cc = 0; cc < 8; cc++) accp[rp][cc] = 0ull;

#pragma unroll 4
  for (int k = 0; k < 64; k++)
    GEMM_STEP(as + k * 128 + r0, w2s + k * 64 + c0);

  float b2v[8];
#pragma unroll
  for (int cc = 0; cc < 8; cc++) b2v[cc] = __ldg(B2 + c0 + cc);
#pragma unroll
  for (int rp = 0; rp < 4; rp++) {
    float rowA[8], rowB[8];
#pragma unroll
    for (int cc = 0; cc < 8; cc++) {
      float2 v = upk2(accp[rp][cc]);
      rowA[cc] = v.x + b2v[cc];
      rowB[cc] = v.y + b2v[cc];
    }
    int gr0 = rb + r0 + 2 * rp;
    if (gr0 < N) {
      __half2* dst = (__half2*)g_Mh4 + (size_t)gr0 * 32 + (c0 >> 1);
      dst[0] = __floats2half2_rn(rowA[0], rowA[1]);
      dst[1] = __floats2half2_rn(rowA[2], rowA[3]);
      dst[2] = __floats2half2_rn(rowA[4], rowA[5]);
      dst[3] = __floats2half2_rn(rowA[6], rowA[7]);
    }
    if (gr0 + 1 < N) {
      __half2* dst = (__half2*)g_Mh4 + (size_t)(gr0 + 1) * 32 + (c0 >> 1);
      dst[0] = __floats2half2_rn(rowB[0], rowB[1]);
      dst[1] = __floats2half2_rn(rowB[2], rowB[3]);
      dst[2] = __floats2half2_rn(rowB[4], rowB[5]);
      dst[3] = __floats2half2_rn(rowB[6], rowB[7]);
    }
  }
}

// ---------------------------------------------------------------------------
// upd: hn = relu([h,agg] @ W1 + b1) @ W2 + b2 ; bn ; h = relu(hn + h)
// ---------------------------------------------------------------------------
__global__ void __launch_bounds__(128) upd_kernel(
    const float* __restrict__ W1, const float* __restrict__ B1,
    const float* __restrict__ W2, const float* __restrict__ B2,
    const float* __restrict__ Gm, const float* __restrict__ Bt,
    const float* __restrict__ Mn, const float* __restrict__ Vr, int N) {
  extern __shared__ float sm[];
  float* as  = sm;                // 128 * 128  ([k][row]; k<64:h, k>=64:agg/t)
  float* w1s = sm + 128 * 128;    // 128 * 64
  float* w2s = w1s + 128 * 64;    // 64 * 64

  float* hio = (float*)g_h4;
  const float* agg = (const float*)g_agg4;
  int tid = threadIdx.x;
  int rb = blockIdx.x * NROWS;

#pragma unroll
  for (int i = tid; i < 2048; i += 128)
    ((float4*)w1s)[i] = __ldg((const float4*)W1 + i);
#pragma unroll
  for (int i = tid; i < 1024; i += 128)
    ((float4*)w2s)[i] = __ldg((const float4*)W2 + i);
  {
    int r = tid, grow = rb + r;
    if (grow < N) {
      const float4* s1 = (const float4*)(hio + (size_t)grow * 64);
      const float4* s2 = (const float4*)(agg + (size_t)grow * 64);
#pragma unroll
      for (int kq = 0; kq < 16; kq++) {
        float4 v = s1[kq];
        as[(kq * 4 + 0) * 128 + r] = v.x;
        as[(kq * 4 + 1) * 128 + r] = v.y;
        as[(kq * 4 + 2) * 128 + r] = v.z;
        as[(kq * 4 + 3) * 128 + r] = v.w;
        float4 u = s2[kq];
        as[(64 + kq * 4 + 0) * 128 + r] = u.x;
        as[(64 + kq * 4 + 1) * 128 + r] = u.y;
        as[(64 + kq * 4 + 2) * 128 + r] = u.z;
        as[(64 + kq * 4 + 3) * 128 + r] = u.w;
      }
    } else {
#pragma unroll
      for (int k = 0; k < 128; k++) as[k * 128 + r] = 0.f;
    }
  }
  __syncthreads();

  int ty = tid >> 3, tx = tid & 7;
  int r0 = ty * 8, c0 = tx * 8;

  u64 accp[4][8];
#pragma unroll
  for (int rp = 0; rp < 4; rp++)
#pragma unroll
    for (int cc = 0; cc < 8; cc++) accp[rp][cc] = 0ull;

#pragma unroll 4
  for (int k = 0; k < 128; k++)
    GEMM_STEP(as + k * 128 + r0, w1s + k * 64 + c0);

  __syncthreads();  // write t into rows [64..128) (agg half no longer needed)
#pragma unroll
  for (int cc = 0; cc < 8; cc++) {
    float b = __ldg(B1 + c0 + cc);
#pragma unroll
    for (int rp = 0; rp < 4; rp++) {
      float2 v = upk2(accp[rp][cc]);
      as[(64 + c0 + cc) * 128 + (r0 + 2 * rp)] = fmaxf(v.x + b, 0.f);
      as[(64 + c0 + cc) * 128 + (r0 + 2 * rp + 1)] = fmaxf(v.y + b, 0.f);
    }
  }
  __syncthreads();

#pragma unroll
  for (int rp = 0; rp < 4; rp++)
#pragma unroll
    for (int cc = 0; cc < 8; cc++) accp[rp][cc] = 0ull;

#pragma unroll 4
  for (int k = 0; k < 64; k++)
    GEMM_STEP(as + (64 + k) * 128 + r0, w2s + k * 64 + c0);

  float sc[8], sh[8], b2v[8];
#pragma unroll
  for (int cc = 0; cc < 8; cc++) {
    int c = c0 + cc;
    float s = __ldg(Gm + c) * rsqrtf(__ldg(Vr + c) + 1e-5f);
    sc[cc] = s;
    sh[cc] = __ldg(Bt + c) - __ldg(Mn + c) * s;
    b2v[cc] = __ldg(B2 + c);
  }
#pragma unroll
  for (int rp = 0; rp < 4; rp++) {
    float rowA[8], rowB[8];
#pragma unroll
    for (int cc = 0; cc < 8; cc++) {
      float2 v = upk2(accp[rp][cc]);
      rowA[cc] = v.x + b2v[cc];
      rowB[cc] = v.y + b2v[cc];
    }
    int lr0 = r0 + 2 * rp;
#pragma unroll
    for (int half = 0; half < 2; half++) {
      int grow = rb + lr0 + half;
      if (grow >= N) continue;
      float* rowv = half ? rowB : rowA;
      float o[8];
#pragma unroll
      for (int cc = 0; cc < 8; cc++) {
        float hold = as[(c0 + cc) * 128 + lr0 + half];  // old h (rows <64)
        o[cc] = fmaxf(fmaf(rowv[cc], sc[cc], sh[cc]) + hold, 0.f);
      }
      float4* dst = (float4*)(hio + (size_t)grow * 64 + c0);
      dst[0] = make_float4(o[0], o[1], o[2], o[3]);
      dst[1] = make_float4(o[4], o[5], o[6], o[7]);
    }
  }
}

// ---------------------------------------------------------------------------
// out = relu(h[:NQ] @ out_w1 + b1) @ out_w2 + b2   (warp per node)
// ---------------------------------------------------------------------------
__global__ void __launch_bounds__(256) out_kernel(
    const float* __restrict__ w1, const float* __restrict__ b1,
    const float* __restrict__ w2, const float* __restrict__ b2,
    float* __restrict__ out, int NQ) {
  int warp = (blockIdx.x * blockDim.x + threadIdx.x) >> 5;
  int lane = threadIdx.x & 31;
  if (warp >= NQ) return;
  const float* h = (const float*)g_h4;
  float2 hv = ((const float2*)(h + (size_t)warp * 64))[lane];
  float acc = __ldg(b1 + lane);
#pragma unroll
  for (int kk = 0; kk < 32; kk++) {
    float hx = __shfl_sync(0xffffffffu, hv.x, kk);
    float hy = __shfl_sync(0xffffffffu, hv.y, kk);
    acc = fmaf(hx, __ldg(w1 + (2 * kk) * 32 + lane), acc);
    acc = fmaf(hy, __ldg(w1 + (2 * kk + 1) * 32 + lane), acc);
  }
  float v = fmaxf(acc, 0.f) * __ldg(w2 + lane);
#pragma unroll
  for (int o = 16; o; o >>= 1) v += __shfl_down_sync(0xffffffffu, v, o);
  if (lane == 0) out[warp] = v + __ldg(b2);
}

// ---------------------------------------------------------------------------
extern "C" void kernel_launch(void* const* d_in, const int* in_sizes, int n_in,
                              void* d_out, int out_size) {
  int off = (n_in >= 21) ? 1 : 0;
  const float* x      = (const float*)d_in[0];
  const int*   ei     = (const int*)d_in[1];
  const float* w_in   = (const float*)d_in[2 + off];
  const float* b_in   = (const float*)d_in[3 + off];
  const float* msg_w1 = (const float*)d_in[4 + off];
  const float* msg_b1 = (const float*)d_in[5 + off];
  const float* msg_w2 = (const float*)d_in[6 + off];
  const float* msg_b2 = (const float*)d_in[7 + off];
  const float* upd_w1 = (const float*)d_in[8 + off];
  const float* upd_b1 = (const float*)d_in[9 + off];
  const float* upd_w2 = (const float*)d_in[10 + off];
  const float* upd_b2 = (const float*)d_in[11 + off];
  const float* bn_g   = (const float*)d_in[12 + off];
  const float* bn_b   = (const float*)d_in[13 + off];
  const float* bn_m   = (const float*)d_in[14 + off];
  const float* bn_v   = (const float*)d_in[15 + off];
  const float* out_w1 = (const float*)d_in[16 + off];
  const float* out_b1 = (const float*)d_in[17 + off];
  const float* out_w2 = (const float*)d_in[18 + off];
  const float* out_b2 = (const float*)d_in[19 + off];

  int N = in_sizes[0] / 3;
  int E = in_sizes[1] / 2;
  int L = in_sizes[4 + off] / (64 * 64);
  int NQ = out_size;

  const int MSG_SMEM = (64 * 128 + 2 * 64 * 64) * 4;          // 64 KB
  const int UPD_SMEM = (128 * 128 + 128 * 64 + 64 * 64) * 4;  // 112 KB
  cudaFuncSetAttribute(msg_kernel, cudaFuncAttributeMaxDynamicSharedMemorySize,
                       MSG_SMEM);
  cudaFuncSetAttribute(upd_kernel, cudaFuncAttributeMaxDynamicSharedMemorySize,
                       UPD_SMEM);

  int gb = (N + NROWS - 1) / NROWS;
  int nb_scan = (N + 1023) / 1024;

  input_kernel<<<(N * 64 + 255) / 256, 256>>>(x, w_in, b_in, N);

  zero_counts_kernel<<<(N + 255) / 256, 256>>>(N);
  hist_kernel<<<(E + 255) / 256, 256>>>(ei, E);
  scan1_kernel<<<nb_scan, 1024>>>(N);
  scan2_kernel<<<1, 32>>>(nb_scan);
  scan3_kernel<<<(N + 255) / 256, 256>>>(N);
  fill_kernel<<<(E + 255) / 256, 256>>>(ei, E);

  for (int l = 0; l < L; l++) {
    msg_kernel<<<gb, 128, MSG_SMEM>>>(msg_w1 + l * 4096, msg_b1 + l * 64,
                                      msg_w2 + l * 4096, msg_b2 + l * 64, N);
    gather_kernel<<<(N * 32 + 255) / 256, 256>>>(N);
    upd_kernel<<<gb, 128, UPD_SMEM>>>(
        upd_w1 + l * 8192, upd_b1 + l * 64, upd_w2 + l * 4096, upd_b2 + l * 64,
        bn_g + l * 64, bn_b + l * 64, bn_m + l * 64, bn_v + l * 64, N);
  }

  out_kernel<<<(NQ * 32 + 255) / 256, 256>>>(out_w1, out_b1, out_w2, out_b2,
                                             (float*)d_out, NQ);
}